// round 17
// baseline (speedup 1.0000x reference)
#include <cuda_runtime.h>
#include <cuda_fp16.h>
#include <cstdint>
#include <math.h>

// Problem constants
#define T_TOK 2048
#define DIM   768
#define HID   3072
#define NE    8
#define CAP   2048
#define SPLITK 4

// k_front role block counts (256-thread blocks)
#define FR_ROUT 2048
#define FR_PREP 1536
#define FR_TR1  (12 * 48 * NE)
#define FR_TR2  (12 * 48 * NE)
#define FR_TOTAL (FR_ROUT + FR_PREP + FR_TR1 + FR_TR2)

// fused task counts
#define N_MMA1 (12 * 16 * NE)   // 1536
#define N_MMA2 (12 * 16 * NE)   // 1536 (3 nt * 4 sk * 16 mt * 8 e)
#define N_TASK (N_MMA1 + N_MMA2)

// ---------------- device scratch ----------------
__device__ int    g_cnt[NE];
__device__ int    g_pair[NE * CAP];
__device__ float  g_tw[T_TOK * 2];
__device__ int    g_task;
__device__ int    g_done[NE * 16];
__device__ __half g_xh[(size_t)T_TOK * DIM];
__device__ __half g_w1h[(size_t)NE * HID * DIM];
__device__ __half g_w2h[(size_t)NE * DIM * HID];
__device__ __half g_hidden[(size_t)NE * CAP * HID];

// ---------------- helpers ----------------
__device__ __forceinline__ uint32_t smem_u32(const void* p) {
    uint32_t a;
    asm("{ .reg .u64 t; cvta.to.shared.u64 t, %1; cvt.u32.u64 %0, t; }" : "=r"(a) : "l"(p));
    return a;
}
#define LDSM4(R, addr) \
    asm volatile("ldmatrix.sync.aligned.m8n8.x4.shared.b16 {%0,%1,%2,%3}, [%4];" \
        : "=r"((R)[0]), "=r"((R)[1]), "=r"((R)[2]), "=r"((R)[3]) : "r"(addr))
#define MMA16(d, a, b0, b1) \
    asm volatile("mma.sync.aligned.m16n8k16.row.col.f32.f16.f16.f32 " \
        "{%0,%1,%2,%3}, {%4,%5,%6,%7}, {%8,%9}, {%0,%1,%2,%3};" \
        : "+f"((d)[0]), "+f"((d)[1]), "+f"((d)[2]), "+f"((d)[3]) \
        : "r"((a)[0]), "r"((a)[1]), "r"((a)[2]), "r"((a)[3]), "r"(b0), "r"(b1))
#define CP16(smem, gmem) \
    asm volatile("cp.async.ca.shared.global [%0], [%1], 16;" :: "r"(smem), "l"(gmem))
#define CP_COMMIT() asm volatile("cp.async.commit_group;" ::: "memory")
#define CP_WAIT1()  asm volatile("cp.async.wait_group 1;" ::: "memory")

// SMEM: tok[128]@0, pw[128]@512, task@1024, A stages @1152 (3x16KB), B stages (3x32KB)
#define SMO_TASK  1024
#define SMO_A(s)  (1152 + (s) * 16384)
#define SMO_B(s)  (1152 + 49152 + (s) * 32768)
#define SMEM_SZ   (1152 + 49152 + 98304)

// ---------------- zero counters ----------------
__global__ void k_zero() {
    int t = threadIdx.x;
    if (t < NE * 16) g_done[t] = 0;
    if (t >= 128 && t < 128 + NE) g_cnt[t - 128] = 0;
    if (t == 136) g_task = 0;
}

// 64x64 fp32->fp16 transpose tile
__device__ __forceinline__ void tr_tile64(const float* __restrict__ src, int sstride,
                                          __half* __restrict__ dst, int dstride,
                                          int r0, int c0, __half* st, int tid) {
    const int row = tid >> 4;
    const int c4  = tid & 15;
    #pragma unroll
    for (int j = 0; j < 4; j++) {
        int r = row + j * 16;
        float4 v = *(const float4*)(src + (size_t)(r0 + r) * sstride + c0 + c4 * 4);
        st[(c4 * 4 + 0) * 66 + r] = __float2half_rn(v.x);
        st[(c4 * 4 + 1) * 66 + r] = __float2half_rn(v.y);
        st[(c4 * 4 + 2) * 66 + r] = __float2half_rn(v.z);
        st[(c4 * 4 + 3) * 66 + r] = __float2half_rn(v.w);
    }
    __syncthreads();
    #pragma unroll
    for (int i = 0; i < 8; i++) {
        int o = tid + 256 * i;
        int crow = o >> 5;
        int pair = o & 31;
        __half2 val = *(__half2*)(st + crow * 66 + pair * 2);
        *(__half2*)(dst + (size_t)(c0 + crow) * dstride + r0 + pair * 2) = val;
    }
}

// ---------------- fused front: router | prep | w1 tr | w2 tr ----------------
__global__ void k_front(const float* __restrict__ x, const float* __restrict__ gw,
                        const float* __restrict__ w1, const float* __restrict__ w2,
                        float* __restrict__ out) {
    __shared__ float red[NE][256];
    __shared__ __align__(16) __half st[64 * 66];
    const int b = blockIdx.x, tid = threadIdx.x;

    if (b < FR_ROUT) {
        const int tok = b;
        float acc[NE];
        #pragma unroll
        for (int e = 0; e < NE; e++) acc[e] = 0.f;
        const float* xr = x + (size_t)tok * DIM;
        for (int d = tid; d < DIM; d += 256) {
            float xv = xr[d];
            #pragma unroll
            for (int e = 0; e < NE; e++) acc[e] += xv * gw[e * DIM + d];
        }
        #pragma unroll
        for (int e = 0; e < NE; e++) red[e][tid] = acc[e];
        __syncthreads();
        for (int s = 128; s > 0; s >>= 1) {
            if (tid < s) {
                #pragma unroll
                for (int e = 0; e < NE; e++) red[e][tid] += red[e][tid + s];
            }
            __syncthreads();
        }
        if (tid == 0) {
            float p[NE];
            float mx = -1e30f;
            #pragma unroll
            for (int e = 0; e < NE; e++) mx = fmaxf(mx, red[e][0]);
            float sum = 0.f;
            #pragma unroll
            for (int e = 0; e < NE; e++) { p[e] = expf(red[e][0] - mx); sum += p[e]; }
            float inv = 1.f / sum;
            #pragma unroll
            for (int e = 0; e < NE; e++) p[e] *= inv;
            int i0 = 0;
            #pragma unroll
            for (int e = 1; e < NE; e++) if (p[e] > p[i0]) i0 = e;
            int i1 = (i0 == 0) ? 1 : 0;
            #pragma unroll
            for (int e = 0; e < NE; e++) if (e != i0 && p[e] > p[i1]) i1 = e;
            float w0 = p[i0], w1v = p[i1];
            float s2 = 1.f / (w0 + w1v + 1e-9f);
            g_tw[tok * 2 + 0] = w0 * s2;
            g_tw[tok * 2 + 1] = w1v * s2;
            int pos0 = atomicAdd(&g_cnt[i0], 1);
            g_pair[i0 * CAP + pos0] = tok * 2 + 0;
            int pos1 = atomicAdd(&g_cnt[i1], 1);
            g_pair[i1 * CAP + pos1] = tok * 2 + 1;
        }
    } else if (b < FR_ROUT + FR_PREP) {
        int i = (b - FR_ROUT) * 256 + tid;
        ((float4*)out)[i] = make_float4(0.f, 0.f, 0.f, 0.f);
        float4 v = ((const float4*)x)[i];
        ((__half2*)g_xh)[2 * i]     = __floats2half2_rn(v.x, v.y);
        ((__half2*)g_xh)[2 * i + 1] = __floats2half2_rn(v.z, v.w);
    } else if (b < FR_ROUT + FR_PREP + FR_TR1) {
        int tb = b - FR_ROUT - FR_PREP;
        const int e = tb / 576;
        const int rem = tb % 576;
        const int d0 = (rem % 12) * 64, h0 = (rem / 12) * 64;
        tr_tile64(w1 + (size_t)e * DIM * HID, HID,
                  g_w1h + (size_t)e * HID * DIM, DIM, d0, h0, st, tid);
    } else {
        int tb = b - FR_ROUT - FR_PREP - FR_TR1;
        const int e = tb / 576;
        const int rem = tb % 576;
        const int h0 = (rem % 48) * 64, d0 = (rem / 48) * 64;
        tr_tile64(w2 + (size_t)e * HID * DIM, DIM,
                  g_w2h + (size_t)e * DIM * HID, HID, h0, d0, st, tid);
    }
}

// ---------------- mma1 tile task ----------------
__device__ __forceinline__ void mma1_task(int task, const float* __restrict__ b1, char* smem) {
    const int nt = task % 12;
    const int mt = (task / 12) % 16;
    const int e  = task / 192;
    const int count = g_cnt[e];
    const int m0 = mt * 128;
    if (m0 >= count) return;

    int* s_tok = (int*)smem;
    const int tid = threadIdx.x, lane = tid & 31, wid = tid >> 5;
    if (tid < 128) {
        int r = m0 + tid;
        s_tok[tid] = (r < count) ? (g_pair[e * CAP + r] >> 1) : 0;
    }
    __syncthreads();

    const uint32_t sb = smem_u32(smem);
    const int f = tid & 7, rg = tid >> 3;
    int tokA[2];
    uint32_t soffA[2], soffB[4];
    #pragma unroll
    for (int i = 0; i < 2; i++) {
        int row = rg + i * 64;
        tokA[i] = s_tok[row];
        soffA[i] = row * 128 + ((f * 16) ^ ((row & 7) << 4));
    }
    #pragma unroll
    for (int i = 0; i < 4; i++) {
        int row = rg + i * 64;
        soffB[i] = row * 128 + ((f * 16) ^ ((row & 7) << 4));
    }
    const __half* bbase = g_w1h + ((size_t)e * HID + nt * 256 + rg) * DIM + f * 8;

    const int KCH = DIM / 64;   // 12
    #pragma unroll
    for (int p = 0; p < 2; p++) {
        uint32_t ab = sb + SMO_A(p), bb = sb + SMO_B(p);
        #pragma unroll
        for (int i = 0; i < 2; i++)
            CP16(ab + soffA[i], g_xh + (size_t)tokA[i] * DIM + p * 64 + f * 8);
        #pragma unroll
        for (int i = 0; i < 4; i++)
            CP16(bb + soffB[i], bbase + (size_t)i * 64 * DIM + p * 64);
        CP_COMMIT();
    }

    const int wm = (wid & 3) * 32, wn = (wid >> 2) * 64;
    const uint32_t xr = (lane & 7) << 4;
    const int a_rowc = wm + (lane & 15);
    const uint32_t a_kh = (lane & 16) ? 16u : 0u;
    const int b_rowc = wn + (lane & 7) + ((lane & 16) ? 8 : 0);
    const uint32_t b_kh = (lane & 8) ? 16u : 0u;

    float acc[2][8][4];
    #pragma unroll
    for (int i = 0; i < 2; i++)
        #pragma unroll
        for (int j = 0; j < 8; j++)
            #pragma unroll
            for (int c = 0; c < 4; c++) acc[i][j][c] = 0.f;

    for (int kc = 0; kc < KCH; kc++) {
        CP_WAIT1();
        __syncthreads();
        const int kn = kc + 2;
        if (kn < KCH) {
            const int sn = kn % 3;
            uint32_t ab = sb + SMO_A(sn), bb = sb + SMO_B(sn);
            #pragma unroll
            for (int i = 0; i < 2; i++)
                CP16(ab + soffA[i], g_xh + (size_t)tokA[i] * DIM + kn * 64 + f * 8);
            #pragma unroll
            for (int i = 0; i < 4; i++)
                CP16(bb + soffB[i], bbase + (size_t)i * 64 * DIM + kn * 64);
        }
        CP_COMMIT();
        const int st = kc % 3;
        const uint32_t bufA = sb + SMO_A(st), bufB = sb + SMO_B(st);
        #pragma unroll
        for (int ks = 0; ks < 4; ks++) {
            uint32_t Af[2][4], Bf[4][4];
            #pragma unroll
            for (int mf = 0; mf < 2; mf++)
                LDSM4(Af[mf], bufA + (uint32_t)((a_rowc + mf * 16) * 128) + (((uint32_t)ks * 32 + a_kh) ^ xr));
            #pragma unroll
            for (int nb = 0; nb < 4; nb++)
                LDSM4(Bf[nb], bufB + (uint32_t)((b_rowc + nb * 16) * 128) + (((uint32_t)ks * 32 + b_kh) ^ xr));
            #pragma unroll
            for (int mf = 0; mf < 2; mf++)
                #pragma unroll
                for (int nf = 0; nf < 8; nf++)
                    MMA16(acc[mf][nf], Af[mf], Bf[nf >> 1][2 * (nf & 1)], Bf[nf >> 1][2 * (nf & 1) + 1]);
        }
    }

    const int col0 = nt * 256 + wn + (lane & 3) * 2;
    float2 bias[8];
    #pragma unroll
    for (int nf = 0; nf < 8; nf++) {
        bias[nf].x = b1[e * HID + col0 + nf * 8];
        bias[nf].y = b1[e * HID + col0 + nf * 8 + 1];
    }
    #pragma unroll
    for (int mf = 0; mf < 2; mf++) {
        #pragma unroll
        for (int h = 0; h < 2; h++) {
            int row = m0 + wm + mf * 16 + (lane >> 2) + h * 8;
            if (row < count) {
                __half* orow = g_hidden + ((size_t)e * CAP + row) * HID;
                #pragma unroll
                for (int nf = 0; nf < 8; nf++) {
                    float v0 = acc[mf][nf][h * 2 + 0] + bias[nf].x;
                    float v1 = acc[mf][nf][h * 2 + 1] + bias[nf].y;
                    float g0 = 0.5f * v0 * (1.0f + erff(v0 * 0.7071067811865476f));
                    float g1 = 0.5f * v1 * (1.0f + erff(v1 * 0.7071067811865476f));
                    *(__half2*)(orow + col0 + nf * 8) = __floats2half2_rn(g0, g1);
                }
            }
        }
    }
    // publish: hidden tile (e, mt, nt) done
    __threadfence();
    __syncthreads();
    if (tid == 0) atomicAdd(&g_done[e * 16 + mt], 1);
}

// ---------------- mma2 tile task (waits on g_done[e][mt] == 12) ----------------
__device__ __forceinline__ void mma2_task(int task, const float* __restrict__ b2,
                                          float* __restrict__ out, char* smem) {
    const int nt = task % 3;
    const int sk = (task / 3) % 4;
    const int mt = (task / 12) % 16;
    const int e  = task / 192;
    const int count = g_cnt[e];
    const int m0 = mt * 128;
    if (m0 >= count) return;

    const int tid = threadIdx.x, lane = tid & 31, wid = tid >> 5;
    if (tid == 0) {
        while (atomicAdd(&g_done[e * 16 + mt], 0) < 12) __nanosleep(200);
    }
    __syncthreads();
    __threadfence();

    int* s_tok = (int*)smem;
    float* s_pw = (float*)(smem + 512);
    if (tid < 128) {
        int r = m0 + tid;
        int pid = (r < count) ? g_pair[e * CAP + r] : 0;
        s_tok[tid] = pid;
        s_pw[tid] = g_tw[pid];
    }
    __syncthreads();

    const uint32_t sb = smem_u32(smem);
    const int f = tid & 7, rg = tid >> 3;
    uint32_t soffA[2], soffB[4];
    #pragma unroll
    for (int i = 0; i < 2; i++) {
        int row = rg + i * 64;
        soffA[i] = row * 128 + ((f * 16) ^ ((row & 7) << 4));
    }
    #pragma unroll
    for (int i = 0; i < 4; i++) {
        int row = rg + i * 64;
        soffB[i] = row * 128 + ((f * 16) ^ ((row & 7) << 4));
    }
    const int k_base = sk * (HID / SPLITK);
    const __half* abase = g_hidden + ((size_t)e * CAP + m0 + rg) * HID + k_base + f * 8;
    const __half* bbase = g_w2h + ((size_t)e * DIM + nt * 256 + rg) * HID + k_base + f * 8;

    const int KCH = HID / SPLITK / 64;   // 12
    #pragma unroll
    for (int p = 0; p < 2; p++) {
        uint32_t ab = sb + SMO_A(p), bb = sb + SMO_B(p);
        #pragma unroll
        for (int i = 0; i < 2; i++)
            CP16(ab + soffA[i], abase + (size_t)i * 64 * HID + p * 64);
        #pragma unroll
        for (int i = 0; i < 4; i++)
            CP16(bb + soffB[i], bbase + (size_t)i * 64 * HID + p * 64);
        CP_COMMIT();
    }

    const int wm = (wid & 3) * 32, wn = (wid >> 2) * 64;
    const uint32_t xr = (lane & 7) << 4;
    const int a_rowc = wm + (lane & 15);
    const uint32_t a_kh = (lane & 16) ? 16u : 0u;
    const int b_rowc = wn + (lane & 7) + ((lane & 16) ? 8 : 0);
    const uint32_t b_kh = (lane & 8) ? 16u : 0u;

    float acc[2][8][4];
    #pragma unroll
    for (int i = 0; i < 2; i++)
        #pragma unroll
        for (int j = 0; j < 8; j++)
            #pragma unroll
            for (int c = 0; c < 4; c++) acc[i][j][c] = 0.f;

    for (int kc = 0; kc < KCH; kc++) {
        CP_WAIT1();
        __syncthreads();
        const int kn = kc + 2;
        if (kn < KCH) {
            const int sn = kn % 3;
            uint32_t ab = sb + SMO_A(sn), bb = sb + SMO_B(sn);
            #pragma unroll
            for (int i = 0; i < 2; i++)
                CP16(ab + soffA[i], abase + (size_t)i * 64 * HID + kn * 64);
            #pragma unroll
            for (int i = 0; i < 4; i++)
                CP16(bb + soffB[i], bbase + (size_t)i * 64 * HID + kn * 64);
        }
        CP_COMMIT();
        const int st = kc % 3;
        const uint32_t bufA = sb + SMO_A(st), bufB = sb + SMO_B(st);
        #pragma unroll
        for (int ks = 0; ks < 4; ks++) {
            uint32_t Af[2][4], Bf[4][4];
            #pragma unroll
            for (int mf = 0; mf < 2; mf++)
                LDSM4(Af[mf], bufA + (uint32_t)((a_rowc + mf * 16) * 128) + (((uint32_t)ks * 32 + a_kh) ^ xr));
            #pragma unroll
            for (int nb = 0; nb < 4; nb++)
                LDSM4(Bf[nb], bufB + (uint32_t)((b_rowc + nb * 16) * 128) + (((uint32_t)ks * 32 + b_kh) ^ xr));
            #pragma unroll
            for (int mf = 0; mf < 2; mf++)
                #pragma unroll
                for (int nf = 0; nf < 8; nf++)
                    MMA16(acc[mf][nf], Af[mf], Bf[nf >> 1][2 * (nf & 1)], Bf[nf >> 1][2 * (nf & 1) + 1]);
        }
    }

    const int col0 = nt * 256 + wn + (lane & 3) * 2;
    float2 bias[8];
    #pragma unroll
    for (int nf = 0; nf < 8; nf++) {
        if (sk == 0) {
            bias[nf].x = b2[e * DIM + col0 + nf * 8];
            bias[nf].y = b2[e * DIM + col0 + nf * 8 + 1];
        } else {
            bias[nf].x = 0.f;
            bias[nf].y = 0.f;
        }
    }
    #pragma unroll
    for (int mf = 0; mf < 2; mf++) {
        #pragma unroll
        for (int h = 0; h < 2; h++) {
            int lrow = wm + mf * 16 + (lane >> 2) + h * 8;
            if (m0 + lrow < count) {
                int pid = s_tok[lrow];
                float pw = s_pw[lrow];
                float* orow = out + (size_t)(pid >> 1) * DIM;
                #pragma unroll
                for (int nf = 0; nf < 8; nf++) {
                    atomicAdd(orow + col0 + nf * 8,     (acc[mf][nf][h * 2 + 0] + bias[nf].x) * pw);
                    atomicAdd(orow + col0 + nf * 8 + 1, (acc[mf][nf][h * 2 + 1] + bias[nf].y) * pw);
                }
            }
        }
    }
}

// ---------------- persistent fused GEMM1+GEMM2 ----------------
__global__ void __launch_bounds__(512, 1)
k_mma_fused(const float* __restrict__ b1, const float* __restrict__ b2,
            float* __restrict__ out) {
    extern __shared__ char smem[];
    int* s_task = (int*)(smem + SMO_TASK);
    const int tid = threadIdx.x;
    while (true) {
        if (tid == 0) *s_task = atomicAdd(&g_task, 1);
        __syncthreads();
        const int t = *s_task;
        __syncthreads();
        if (t >= N_TASK) return;
        if (t < N_MMA1) mma1_task(t, b1, smem);
        else            mma2_task(t - N_MMA1, b2, out, smem);
    }
}

// ---------------- launch ----------------
extern "C" void kernel_launch(void* const* d_in, const int* in_sizes, int n_in,
                              void* d_out, int out_size) {
    const float* x  = (const float*)d_in[0];
    const float* gw = (const float*)d_in[1];
    const float* w1 = (const float*)d_in[2];
    const float* b1 = (const float*)d_in[3];
    const float* w2 = (const float*)d_in[4];
    const float* b2 = (const float*)d_in[5];
    float* out = (float*)d_out;

    cudaFuncSetAttribute(k_mma_fused, cudaFuncAttributeMaxDynamicSharedMemorySize, SMEM_SZ);

    k_zero<<<1, 256>>>();
    k_front<<<FR_TOTAL, 256>>>(x, gw, w1, w2, out);
    k_mma_fused<<<148, 512, SMEM_SZ>>>(b1, b2, out);
}